// round 2
// baseline (speedup 1.0000x reference)
#include <cuda_runtime.h>

// CIN (xDeepFM) fused 3-layer kernel, fp32 FFMA2, round 2.
// Key changes vs round 1:
//  - W pre-duplicated into Wd[k][2h] = (w,w) so the FFMA2 broadcast operand is
//    loaded as an aligned register pair (no per-g MOV packing).
//  - 128 threads/CTA, warp w owns h in [32w,32w+32), thread tile 4h x 8d,
//    accumulators packed over d (16 x f32x2).
//  - smem 36KB (osum aliased into zs) -> 6 CTAs/SM = 24 warps.

#define F0c 32
#define Dc  32
#define Hc  128
#define NT  128

#define KTOT (1024 + 4096 + 4096)   // 9216 rows of W total

__device__ float Wd_buf[KTOT * 2 * Hc];   // duplicated weights, 9.4 MB

__device__ __forceinline__ void upk2(unsigned long long v, float& lo, float& hi) {
    asm("mov.b64 {%0,%1}, %2;" : "=f"(lo), "=f"(hi) : "l"(v));
}
__device__ __forceinline__ unsigned long long fma2(unsigned long long a,
                                                   unsigned long long b,
                                                   unsigned long long c) {
    unsigned long long r;
    asm("fma.rn.f32x2 %0, %1, %2, %3;" : "=l"(r) : "l"(a), "l"(b), "l"(c));
    return r;
}
__device__ __forceinline__ unsigned long long mul2(unsigned long long a,
                                                   unsigned long long b) {
    unsigned long long r;
    asm("mul.rn.f32x2 %0, %1, %2;" : "=l"(r) : "l"(a), "l"(b));
    return r;
}

// Prep: Wd[k][2h] = Wd[k][2h+1] = W[k][h]
__global__ void dup_w_kernel(const float* __restrict__ W0,
                             const float* __restrict__ W1,
                             const float* __restrict__ W2) {
    int i = blockIdx.x * blockDim.x + threadIdx.x;   // over KTOT*128
    if (i >= KTOT * Hc) return;
    int k = i >> 7;
    int h = i & (Hc - 1);
    float v;
    if (k < 1024)      v = W0[k * Hc + h];
    else if (k < 5120) v = W1[(k - 1024) * Hc + h];
    else               v = W2[(k - 5120) * Hc + h];
    float2 d2 = make_float2(v, v);
    ((float2*)Wd_buf)[(size_t)k * Hc + h] = d2;
}

__global__ void __launch_bounds__(NT, 5)
cin_kernel(const float* __restrict__ X,
           const float* __restrict__ Bias0, const float* __restrict__ Bias1,
           const float* __restrict__ Bias2,
           float* __restrict__ out)
{
    __shared__ __align__(16) float x0s[F0c * Dc];   // 4 KB
    __shared__ __align__(16) float st[Hc * Dc];     // 16 KB (state)
    __shared__ __align__(16) float zs[Hc * Dc];     // 16 KB (z for current f; tail aliased as osum)
    float* osum = zs;                               // [4][128] partial d-sums (epilogue only)

    const int b    = blockIdx.x;
    const int t    = threadIdx.x;
    const int w    = t >> 5;
    const int lane = t & 31;
    const int hg   = lane & 7;        // 8 h-groups of 4 within warp
    const int dg   = lane >> 3;       // 4 d-groups of 8 within warp
    const int h0   = (w << 5) + (hg << 2);
    const int d0   = dg << 3;
    const int tq   = t & 7;           // this thread's quad column in z-build

    // Load x0; initialize state = x0
    {
        const float4* Xv  = (const float4*)(X + (size_t)b * (F0c * Dc));
        float4* x0v = (float4*)x0s;
        float4* stv = (float4*)st;
        #pragma unroll
        for (int i = t; i < F0c * Dc / 4; i += NT) {
            float4 v = Xv[i];
            x0v[i] = v;
            stv[i] = v;
        }
    }

    float* outb = out + (size_t)b * (3 * Hc);
    const unsigned long long* __restrict__ Wd =
        (const unsigned long long*)Wd_buf;   // one ull per (k,h)

    size_t layer_base = 0;   // row offset into Wd

    for (int layer = 0; layer < 3; ++layer) {
        const int fk = (layer == 0) ? F0c : Hc;
        const float* Bv = (layer == 0) ? Bias0 : ((layer == 1) ? Bias1 : Bias2);

        unsigned long long acc[4][4];
        #pragma unroll
        for (int j = 0; j < 4; ++j)
            #pragma unroll
            for (int i = 0; i < 4; ++i) acc[j][i] = 0ull;

        for (int f = 0; f < F0c; ++f) {
            __syncthreads();   // prev f's zs readers done; st/x0 writes visible

            // z[g][d] = x0[f][d] * state[g][d], cooperatively, f32x2 muls.
            // Thread's float4 column is fixed (tq) since NT % 8 == 0.
            {
                ulonglong2 xq = *(const ulonglong2*)(x0s + f * Dc + (tq << 2));
                const ulonglong2* sv2 = (const ulonglong2*)st;
                ulonglong2* zv = (ulonglong2*)zs;
                const int n4 = fk * (Dc / 4);
                #pragma unroll 4
                for (int i = t; i < n4; i += NT) {
                    ulonglong2 sv = sv2[i];
                    ulonglong2 r;
                    r.x = mul2(xq.x, sv.x);
                    r.y = mul2(xq.y, sv.y);
                    zv[i] = r;
                }
            }
            __syncthreads();

            const unsigned long long* wp = Wd + (layer_base + (size_t)f * fk) * Hc + h0;
            const float* zrow = zs + d0;

            #pragma unroll 4
            for (int g = 0; g < fk; ++g) {
                ulonglong2 wa = *(const ulonglong2*)wp;        // (w_h0,w_h0),(w_h1,w_h1)
                ulonglong2 wb = *(const ulonglong2*)(wp + 2);  // h0+2, h0+3
                ulonglong2 z0 = *(const ulonglong2*)zrow;      // d0..d0+3
                ulonglong2 z1 = *(const ulonglong2*)(zrow + 4);// d0+4..d0+7
                wp   += Hc;
                zrow += Dc;
                acc[0][0] = fma2(wa.x, z0.x, acc[0][0]);
                acc[0][1] = fma2(wa.x, z0.y, acc[0][1]);
                acc[0][2] = fma2(wa.x, z1.x, acc[0][2]);
                acc[0][3] = fma2(wa.x, z1.y, acc[0][3]);
                acc[1][0] = fma2(wa.y, z0.x, acc[1][0]);
                acc[1][1] = fma2(wa.y, z0.y, acc[1][1]);
                acc[1][2] = fma2(wa.y, z1.x, acc[1][2]);
                acc[1][3] = fma2(wa.y, z1.y, acc[1][3]);
                acc[2][0] = fma2(wb.x, z0.x, acc[2][0]);
                acc[2][1] = fma2(wb.x, z0.y, acc[2][1]);
                acc[2][2] = fma2(wb.x, z1.x, acc[2][2]);
                acc[2][3] = fma2(wb.x, z1.y, acc[2][3]);
                acc[3][0] = fma2(wb.y, z0.x, acc[3][0]);
                acc[3][1] = fma2(wb.y, z0.y, acc[3][1]);
                acc[3][2] = fma2(wb.y, z1.x, acc[3][2]);
                acc[3][3] = fma2(wb.y, z1.y, acc[3][3]);
            }
        }
        __syncthreads();   // all zs/st reads complete (also guards osum alias)

        // Epilogue: bias, new state, partial d-sums
        {
            const float4 bq = ((const float4*)Bv)[h0 >> 2];
            const float bj[4] = {bq.x, bq.y, bq.z, bq.w};
            #pragma unroll
            for (int j = 0; j < 4; ++j) {
                float v[8];
                float s = 0.f;
                #pragma unroll
                for (int i = 0; i < 4; ++i) {
                    float lo, hi;
                    upk2(acc[j][i], lo, hi);
                    lo += bj[j];
                    hi += bj[j];
                    v[2 * i]     = lo;
                    v[2 * i + 1] = hi;
                    s += lo + hi;
                }
                float4* strow = (float4*)(st + (h0 + j) * Dc + d0);
                strow[0] = make_float4(v[0], v[1], v[2], v[3]);
                strow[1] = make_float4(v[4], v[5], v[6], v[7]);
                osum[dg * Hc + (h0 + j)] = s;
            }
        }
        __syncthreads();
        // Reduce the 4 d-group partials; thread t owns output h = t
        {
            float o = osum[0 * Hc + t] + osum[1 * Hc + t] +
                      osum[2 * Hc + t] + osum[3 * Hc + t];
            outb[layer * Hc + t] = o;
        }

        layer_base += (size_t)F0c * fk;
    }
}

extern "C" void kernel_launch(void* const* d_in, const int* in_sizes, int n_in,
                              void* d_out, int out_size) {
    const float* X  = (const float*)d_in[0];
    const float* W0 = (const float*)d_in[1];
    const float* W1 = (const float*)d_in[2];
    const float* W2 = (const float*)d_in[3];
    const float* B0 = (const float*)d_in[4];
    const float* B1 = (const float*)d_in[5];
    const float* B2 = (const float*)d_in[6];
    float* out = (float*)d_out;

    const int B = in_sizes[0] / (F0c * Dc);

    // Build duplicated weights (graph-capturable, deterministic, reruns each call)
    const int total = KTOT * Hc;
    dup_w_kernel<<<(total + 255) / 256, 256>>>(W0, W1, W2);

    cin_kernel<<<B, NT>>>(X, B0, B1, B2, out);
}

// round 3
// speedup vs baseline: 1.0003x; 1.0003x over previous
#include <cuda_runtime.h>

// CIN (xDeepFM) fused 3-layer kernel, fp32 FFMA2, round 2.
// Key changes vs round 1:
//  - W pre-duplicated into Wd[k][2h] = (w,w) so the FFMA2 broadcast operand is
//    loaded as an aligned register pair (no per-g MOV packing).
//  - 128 threads/CTA, warp w owns h in [32w,32w+32), thread tile 4h x 8d,
//    accumulators packed over d (16 x f32x2).
//  - smem 36KB (osum aliased into zs) -> 6 CTAs/SM = 24 warps.

#define F0c 32
#define Dc  32
#define Hc  128
#define NT  128

#define KTOT (1024 + 4096 + 4096)   // 9216 rows of W total

__device__ float Wd_buf[KTOT * 2 * Hc];   // duplicated weights, 9.4 MB

__device__ __forceinline__ void upk2(unsigned long long v, float& lo, float& hi) {
    asm("mov.b64 {%0,%1}, %2;" : "=f"(lo), "=f"(hi) : "l"(v));
}
__device__ __forceinline__ unsigned long long fma2(unsigned long long a,
                                                   unsigned long long b,
                                                   unsigned long long c) {
    unsigned long long r;
    asm("fma.rn.f32x2 %0, %1, %2, %3;" : "=l"(r) : "l"(a), "l"(b), "l"(c));
    return r;
}
__device__ __forceinline__ unsigned long long mul2(unsigned long long a,
                                                   unsigned long long b) {
    unsigned long long r;
    asm("mul.rn.f32x2 %0, %1, %2;" : "=l"(r) : "l"(a), "l"(b));
    return r;
}

// Prep: Wd[k][2h] = Wd[k][2h+1] = W[k][h]
__global__ void dup_w_kernel(const float* __restrict__ W0,
                             const float* __restrict__ W1,
                             const float* __restrict__ W2) {
    int i = blockIdx.x * blockDim.x + threadIdx.x;   // over KTOT*128
    if (i >= KTOT * Hc) return;
    int k = i >> 7;
    int h = i & (Hc - 1);
    float v;
    if (k < 1024)      v = W0[k * Hc + h];
    else if (k < 5120) v = W1[(k - 1024) * Hc + h];
    else               v = W2[(k - 5120) * Hc + h];
    float2 d2 = make_float2(v, v);
    ((float2*)Wd_buf)[(size_t)k * Hc + h] = d2;
}

__global__ void __launch_bounds__(NT, 5)
cin_kernel(const float* __restrict__ X,
           const float* __restrict__ Bias0, const float* __restrict__ Bias1,
           const float* __restrict__ Bias2,
           float* __restrict__ out)
{
    __shared__ __align__(16) float x0s[F0c * Dc];   // 4 KB
    __shared__ __align__(16) float st[Hc * Dc];     // 16 KB (state)
    __shared__ __align__(16) float zs[Hc * Dc];     // 16 KB (z for current f; tail aliased as osum)
    float* osum = zs;                               // [4][128] partial d-sums (epilogue only)

    const int b    = blockIdx.x;
    const int t    = threadIdx.x;
    const int w    = t >> 5;
    const int lane = t & 31;
    const int hg   = lane & 7;        // 8 h-groups of 4 within warp
    const int dg   = lane >> 3;       // 4 d-groups of 8 within warp
    const int h0   = (w << 5) + (hg << 2);
    const int d0   = dg << 3;
    const int tq   = t & 7;           // this thread's quad column in z-build

    // Load x0; initialize state = x0
    {
        const float4* Xv  = (const float4*)(X + (size_t)b * (F0c * Dc));
        float4* x0v = (float4*)x0s;
        float4* stv = (float4*)st;
        #pragma unroll
        for (int i = t; i < F0c * Dc / 4; i += NT) {
            float4 v = Xv[i];
            x0v[i] = v;
            stv[i] = v;
        }
    }

    float* outb = out + (size_t)b * (3 * Hc);
    const unsigned long long* __restrict__ Wd =
        (const unsigned long long*)Wd_buf;   // one ull per (k,h)

    size_t layer_base = 0;   // row offset into Wd

    for (int layer = 0; layer < 3; ++layer) {
        const int fk = (layer == 0) ? F0c : Hc;
        const float* Bv = (layer == 0) ? Bias0 : ((layer == 1) ? Bias1 : Bias2);

        unsigned long long acc[4][4];
        #pragma unroll
        for (int j = 0; j < 4; ++j)
            #pragma unroll
            for (int i = 0; i < 4; ++i) acc[j][i] = 0ull;

        for (int f = 0; f < F0c; ++f) {
            __syncthreads();   // prev f's zs readers done; st/x0 writes visible

            // z[g][d] = x0[f][d] * state[g][d], cooperatively, f32x2 muls.
            // Thread's float4 column is fixed (tq) since NT % 8 == 0.
            {
                ulonglong2 xq = *(const ulonglong2*)(x0s + f * Dc + (tq << 2));
                const ulonglong2* sv2 = (const ulonglong2*)st;
                ulonglong2* zv = (ulonglong2*)zs;
                const int n4 = fk * (Dc / 4);
                #pragma unroll 4
                for (int i = t; i < n4; i += NT) {
                    ulonglong2 sv = sv2[i];
                    ulonglong2 r;
                    r.x = mul2(xq.x, sv.x);
                    r.y = mul2(xq.y, sv.y);
                    zv[i] = r;
                }
            }
            __syncthreads();

            const unsigned long long* wp = Wd + (layer_base + (size_t)f * fk) * Hc + h0;
            const float* zrow = zs + d0;

            #pragma unroll 4
            for (int g = 0; g < fk; ++g) {
                ulonglong2 wa = *(const ulonglong2*)wp;        // (w_h0,w_h0),(w_h1,w_h1)
                ulonglong2 wb = *(const ulonglong2*)(wp + 2);  // h0+2, h0+3
                ulonglong2 z0 = *(const ulonglong2*)zrow;      // d0..d0+3
                ulonglong2 z1 = *(const ulonglong2*)(zrow + 4);// d0+4..d0+7
                wp   += Hc;
                zrow += Dc;
                acc[0][0] = fma2(wa.x, z0.x, acc[0][0]);
                acc[0][1] = fma2(wa.x, z0.y, acc[0][1]);
                acc[0][2] = fma2(wa.x, z1.x, acc[0][2]);
                acc[0][3] = fma2(wa.x, z1.y, acc[0][3]);
                acc[1][0] = fma2(wa.y, z0.x, acc[1][0]);
                acc[1][1] = fma2(wa.y, z0.y, acc[1][1]);
                acc[1][2] = fma2(wa.y, z1.x, acc[1][2]);
                acc[1][3] = fma2(wa.y, z1.y, acc[1][3]);
                acc[2][0] = fma2(wb.x, z0.x, acc[2][0]);
                acc[2][1] = fma2(wb.x, z0.y, acc[2][1]);
                acc[2][2] = fma2(wb.x, z1.x, acc[2][2]);
                acc[2][3] = fma2(wb.x, z1.y, acc[2][3]);
                acc[3][0] = fma2(wb.y, z0.x, acc[3][0]);
                acc[3][1] = fma2(wb.y, z0.y, acc[3][1]);
                acc[3][2] = fma2(wb.y, z1.x, acc[3][2]);
                acc[3][3] = fma2(wb.y, z1.y, acc[3][3]);
            }
        }
        __syncthreads();   // all zs/st reads complete (also guards osum alias)

        // Epilogue: bias, new state, partial d-sums
        {
            const float4 bq = ((const float4*)Bv)[h0 >> 2];
            const float bj[4] = {bq.x, bq.y, bq.z, bq.w};
            #pragma unroll
            for (int j = 0; j < 4; ++j) {
                float v[8];
                float s = 0.f;
                #pragma unroll
                for (int i = 0; i < 4; ++i) {
                    float lo, hi;
                    upk2(acc[j][i], lo, hi);
                    lo += bj[j];
                    hi += bj[j];
                    v[2 * i]     = lo;
                    v[2 * i + 1] = hi;
                    s += lo + hi;
                }
                float4* strow = (float4*)(st + (h0 + j) * Dc + d0);
                strow[0] = make_float4(v[0], v[1], v[2], v[3]);
                strow[1] = make_float4(v[4], v[5], v[6], v[7]);
                osum[dg * Hc + (h0 + j)] = s;
            }
        }
        __syncthreads();
        // Reduce the 4 d-group partials; thread t owns output h = t
        {
            float o = osum[0 * Hc + t] + osum[1 * Hc + t] +
                      osum[2 * Hc + t] + osum[3 * Hc + t];
            outb[layer * Hc + t] = o;
        }

        layer_base += (size_t)F0c * fk;
    }
}

extern "C" void kernel_launch(void* const* d_in, const int* in_sizes, int n_in,
                              void* d_out, int out_size) {
    const float* X  = (const float*)d_in[0];
    const float* W0 = (const float*)d_in[1];
    const float* W1 = (const float*)d_in[2];
    const float* W2 = (const float*)d_in[3];
    const float* B0 = (const float*)d_in[4];
    const float* B1 = (const float*)d_in[5];
    const float* B2 = (const float*)d_in[6];
    float* out = (float*)d_out;

    const int B = in_sizes[0] / (F0c * Dc);

    // Build duplicated weights (graph-capturable, deterministic, reruns each call)
    const int total = KTOT * Hc;
    dup_w_kernel<<<(total + 255) / 256, 256>>>(W0, W1, W2);

    cin_kernel<<<B, NT>>>(X, B0, B1, B2, out);
}

// round 5
// speedup vs baseline: 5.3333x; 5.3319x over previous
#include <cuda_runtime.h>
#include <cuda_bf16.h>
#include <cstdint>

// CIN (xDeepFM) fused 3-layer kernel via mma.sync (HMMA) bf16 3-term split.
// GEMM view per layer: C[(b,d), h] = sum_k Z[(b,d),k] * W[k,h],
//   Z[(b,d), f*fk+g] = x0[b,f,d] * state[b,g,d].
// CTA = 4 batches -> M=128 rows (b_local*32 + d), N=128 (h), K = 32*fk.
// A-fragments built in registers from fp32 smem (state, x0t); split into
// bf16 hi/lo; C = Zh*Wh + Zl*Wh + Zh*Wl in fp32 accumulators.
// W pre-split to bf16 hi/lo 16k-chunks in GMEM by prep kernel; double-buffered
// in smem; B frags via ldmatrix.x4 from 48B-padded [n][k] rows.

#define NT 256
#define KCH 576            // total 16-wide k chunks: 64 + 256 + 256
#define CHUNK_GBYTES 8192  // compact gmem chunk: 2 terms * 128n * 16k * 2B
#define WROW 48            // padded smem bytes per n-row (16k bf16 = 32B -> 48B)
#define WTERM (128 * WROW) // 6144
#define WSTAGE (2 * WTERM) // 12288

// smem byte offsets
#define SM_X0T   0                  // 128 rows * 36 f32 = 18432
#define SM_ST    18432              // 128 rows * 132 f32 = 67584
#define SM_W     86016              // 2 stages * 12288 = 24576
#define SM_BIAS  110592             // 384 f32 = 1536
#define SMEM_TOTAL 112128

__device__ __align__(16) unsigned char WT_buf[KCH * CHUNK_GBYTES]; // 4.5 MB

// ------------- helpers -------------
__device__ __forceinline__ uint32_t smem_u32(const void* p) {
    uint32_t a;
    asm("{ .reg .u64 t; cvta.to.shared.u64 t, %1; cvt.u32.u64 %0, t; }" : "=r"(a) : "l"(p));
    return a;
}
__device__ __forceinline__ uint32_t pkbf(float lo, float hi) {
    uint32_t r;  // first asm operand -> high half
    asm("cvt.rn.bf16x2.f32 %0, %1, %2;" : "=r"(r) : "f"(hi), "f"(lo));
    return r;
}
__device__ __forceinline__ float bflo(uint32_t p) { return __uint_as_float(p << 16); }
__device__ __forceinline__ float bfhi(uint32_t p) { return __uint_as_float(p & 0xffff0000u); }

__device__ __forceinline__ void ldsm4(uint32_t a, uint32_t& r0, uint32_t& r1,
                                      uint32_t& r2, uint32_t& r3) {
    asm volatile("ldmatrix.sync.aligned.m8n8.x4.shared.b16 {%0,%1,%2,%3}, [%4];"
                 : "=r"(r0), "=r"(r1), "=r"(r2), "=r"(r3) : "r"(a));
}
__device__ __forceinline__ void mma16816(float* c, const uint32_t* a, uint32_t b0, uint32_t b1) {
    asm volatile("mma.sync.aligned.m16n8k16.row.col.f32.bf16.bf16.f32 "
                 "{%0,%1,%2,%3}, {%4,%5,%6,%7}, {%8,%9}, {%0,%1,%2,%3};"
                 : "+f"(c[0]), "+f"(c[1]), "+f"(c[2]), "+f"(c[3])
                 : "r"(a[0]), "r"(a[1]), "r"(a[2]), "r"(a[3]), "r"(b0), "r"(b1));
}

// ------------- prep: split W -> bf16 hi/lo, chunked [chunk][term][n][k] -------------
__global__ void prep_w(const float* __restrict__ W0, const float* __restrict__ W1,
                       const float* __restrict__ W2) {
    int i = blockIdx.x * blockDim.x + threadIdx.x;   // over 9216*128
    if (i >= 9216 * 128) return;
    int k = i >> 7, n = i & 127;
    float w;
    if (k < 1024)      w = W0[k * 128 + n];
    else if (k < 5120) w = W1[(k - 1024) * 128 + n];
    else               w = W2[(k - 5120) * 128 + n];
    __nv_bfloat16 hb = __float2bfloat16(w);
    __nv_bfloat16 lb = __float2bfloat16(w - __bfloat162float(hb));
    int c = k >> 4, kk = k & 15;
    unsigned char* base = WT_buf + (size_t)c * CHUNK_GBYTES + n * 32 + kk * 2;
    *(__nv_bfloat16*)(base)        = hb;   // term 0
    *(__nv_bfloat16*)(base + 4096) = lb;   // term 1
}

// ------------- main kernel -------------
__global__ void __launch_bounds__(NT, 2)
cin_hmma_kernel(const float* __restrict__ X,
                const float* __restrict__ B0, const float* __restrict__ B1,
                const float* __restrict__ B2, float* __restrict__ out)
{
    extern __shared__ __align__(16) char smem[];
    float* x0t  = (float*)(smem + SM_X0T);   // [row][36] (f stride)
    float* st   = (float*)(smem + SM_ST);    // [row][132] (g stride)
    float* bias = (float*)(smem + SM_BIAS);  // [384]
    const uint32_t wsm = smem_u32(smem) + SM_W;

    const int tid = threadIdx.x, wid = tid >> 5, lane = tid & 31;
    const int wm = wid >> 1, wn = wid & 1;     // warp grid 4(m=batch) x 2(n)
    const int b0g = blockIdx.x * 4;
    const int r0 = lane >> 2;                  // row-in-frag 0..7
    const int c0 = (lane & 3) * 2;             // col pair base

    // ---- load x0 transposed + init state + bias ----
    {
        const float* Xb = X + (size_t)b0g * 1024;
        for (int i = tid; i < 4096; i += NT) {
            int b = i >> 10, f = (i >> 5) & 31, d = i & 31;
            float v = Xb[i];
            int row = b * 32 + d;
            x0t[row * 36 + f] = v;
            st[row * 132 + f] = v;     // layer-0 state = x0 (g = f)
        }
        for (int i = tid; i < 128; i += NT) {
            bias[i] = B0[i]; bias[128 + i] = B1[i]; bias[256 + i] = B2[i];
        }
    }

    // ---- W double-buffer prefetch of chunk 0 ----
    float4 wreg[2];
    {
        const float4* p = (const float4*)(WT_buf);
        wreg[0] = p[tid * 2]; wreg[1] = p[tid * 2 + 1];
    }
    __syncthreads();
    // store chunk 0 to stage 0
    {
        #pragma unroll
        for (int j = 0; j < 2; ++j) {
            int u = tid * 2 + j;                 // 16B unit in compact chunk
            int term = u >> 8, n = (u >> 1) & 127, kh = u & 1;
            *(float4*)(smem + SM_W + term * WTERM + n * WROW + kh * 16) = wreg[j];
        }
    }
    __syncthreads();

    int cg = 0;  // global chunk counter

    #pragma unroll 1
    for (int l = 0; l < 3; ++l) {
        const int lg2 = (l == 0) ? 1 : 3;        // chunks per f = fk/16
        const int nchunk = (l == 0) ? 64 : 256;

        float acc[2][8][4];
        #pragma unroll
        for (int fr = 0; fr < 2; ++fr)
            #pragma unroll
            for (int nt = 0; nt < 8; ++nt)
                #pragma unroll
                for (int q = 0; q < 4; ++q) acc[fr][nt][q] = 0.f;

        #pragma unroll 1
        for (int cc = 0; cc < nchunk; ++cc) {
            const uint32_t stage = wsm + (uint32_t)(cg & 1) * WSTAGE;

            // prefetch next chunk (global) into regs
            if (cg + 1 < KCH) {
                const float4* p = (const float4*)(WT_buf + (size_t)(cg + 1) * CHUNK_GBYTES);
                wreg[0] = p[tid * 2]; wreg[1] = p[tid * 2 + 1];
            }

            // ---- build A fragments (hi/lo) in registers ----
            const int f = cc >> lg2;
            const int gbase = (cc & ((1 << lg2) - 1)) << 4;
            const int g0 = gbase + c0;
            uint32_t ah[2][4], al[2][4];
            #pragma unroll
            for (int fr = 0; fr < 2; ++fr) {
                #pragma unroll
                for (int j2 = 0; j2 < 2; ++j2) {
                    const int row = wm * 32 + r0 + fr * 16 + j2 * 8;
                    const float x = x0t[row * 36 + f];
                    const float2 p0 = *(const float2*)(st + row * 132 + g0);
                    const float2 p1 = *(const float2*)(st + row * 132 + g0 + 8);
                    float z00 = x * p0.x, z01 = x * p0.y;
                    float z10 = x * p1.x, z11 = x * p1.y;
                    uint32_t h0 = pkbf(z00, z01), h1 = pkbf(z10, z11);
                    al[fr][j2]     = pkbf(z00 - bflo(h0), z01 - bfhi(h0));
                    al[fr][2 + j2] = pkbf(z10 - bflo(h1), z11 - bfhi(h1));
                    ah[fr][j2]     = h0;
                    ah[fr][2 + j2] = h1;
                }
            }

            // ---- B frags (ldmatrix) + MMAs: Zh*Wh, Zl*Wh, Zh*Wl ----
            const int ntile_hl = (lane >> 4) & 1;      // 0/1 within x4 group
            const int kh = (lane >> 3) & 1;
            const int nrow_in = (lane & 7);
            #pragma unroll
            for (int t = 0; t < 2; ++t) {
                const uint32_t tb = stage + t * WTERM;
                #pragma unroll
                for (int j = 0; j < 4; ++j) {
                    const int nrow = (wn * 8 + 2 * j + ntile_hl) * 8 + nrow_in;
                    uint32_t b0r, b1r, b2r, b3r;
                    ldsm4(tb + nrow * WROW + kh * 16, b0r, b1r, b2r, b3r);
                    #pragma unroll
                    for (int fr = 0; fr < 2; ++fr) {
                        if (t == 0) {
                            mma16816(acc[fr][2 * j],     ah[fr], b0r, b1r);
                            mma16816(acc[fr][2 * j],     al[fr], b0r, b1r);
                            mma16816(acc[fr][2 * j + 1], ah[fr], b2r, b3r);
                            mma16816(acc[fr][2 * j + 1], al[fr], b2r, b3r);
                        } else {
                            mma16816(acc[fr][2 * j],     ah[fr], b0r, b1r);
                            mma16816(acc[fr][2 * j + 1], ah[fr], b2r, b3r);
                        }
                    }
                }
            }

            // ---- store prefetched chunk to other stage ----
            if (cg + 1 < KCH) {
                #pragma unroll
                for (int j = 0; j < 2; ++j) {
                    int u = tid * 2 + j;
                    int term = u >> 8, n = (u >> 1) & 127, kh2 = u & 1;
                    *(float4*)(smem + SM_W + ((cg + 1) & 1) * WSTAGE +
                               term * WTERM + n * WROW + kh2 * 16) = wreg[j];
                }
            }
            __syncthreads();
            ++cg;
        }

        // ---- epilogue: output reduction (sum over d) + state update ----
        const int bgl = b0g + wm;
        #pragma unroll
        for (int nt = 0; nt < 8; ++nt) {
            float s0 = acc[0][nt][0] + acc[0][nt][2] + acc[1][nt][0] + acc[1][nt][2];
            float s1 = acc[0][nt][1] + acc[0][nt][3] + acc[1][nt][1] + acc[1][nt][3];
            #pragma unroll
            for (int off = 4; off <= 16; off <<= 1) {
                s0 += __shfl_xor_sync(0xffffffffu, s0, off);
                s1 += __shfl_xor_sync(0xffffffffu, s1, off);
            }
            if (lane < 4) {
                const int col = wn * 64 + nt * 8 + c0;
                float2 o;
                o.x = s0 + 32.0f * bias[l * 128 + col];
                o.y = s1 + 32.0f * bias[l * 128 + col + 1];
                *(float2*)(out + (size_t)bgl * 384 + l * 128 + col) = o;
            }
        }

        if (l < 2) {
            // state[row][h] = C[row][h] + bias_l[h]
            #pragma unroll
            for (int fr = 0; fr < 2; ++fr) {
                #pragma unroll
                for (int nt = 0; nt < 8; ++nt) {
                    const int col = wn * 64 + nt * 8 + c0;
                    const float bx = bias[l * 128 + col];
                    const float by = bias[l * 128 + col + 1];
                    const int rowa = wm * 32 + r0 + fr * 16;
                    float2 v0, v1;
                    v0.x = acc[fr][nt][0] + bx; v0.y = acc[fr][nt][1] + by;
                    v1.x = acc[fr][nt][2] + bx; v1.y = acc[fr][nt][3] + by;
                    *(float2*)(st + rowa * 132 + col)       = v0;
                    *(float2*)(st + (rowa + 8) * 132 + col) = v1;
                }
            }
            __syncthreads();   // state visible before next layer's A builds
        }
    }
}

extern "C" void kernel_launch(void* const* d_in, const int* in_sizes, int n_in,
                              void* d_out, int out_size) {
    const float* X  = (const float*)d_in[0];
    const float* W0 = (const float*)d_in[1];
    const float* W1 = (const float*)d_in[2];
    const float* W2 = (const float*)d_in[3];
    const float* B0 = (const float*)d_in[4];
    const float* B1 = (const float*)d_in[5];
    const float* B2 = (const float*)d_in[6];
    float* out = (float*)d_out;

    const int B = in_sizes[0] / 1024;

    static int smem_set = 0;
    if (!smem_set) {
        cudaFuncSetAttribute(cin_hmma_kernel,
                             cudaFuncAttributeMaxDynamicSharedMemorySize, SMEM_TOTAL);
        smem_set = 1;
    }

    prep_w<<<(9216 * 128 + 255) / 256, 256>>>(W0, W1, W2);
    cin_hmma_kernel<<<B / 4, NT, SMEM_TOTAL>>>(X, B0, B1, B2, out);
}